// round 6
// baseline (speedup 1.0000x reference)
#include <cuda_runtime.h>

// Problem shape (fixed by the dataset)
#define B_ROWS   16384
#define D_DIM    2048
#define D4       (D_DIM / 4)          // 512 float4 per row
#define NBLK     2048
#define NTHR     256                   // 8 warps/block, 1 warp per row
#define WARPS_PER_BLK (NTHR / 32)

__device__ float g_partials[NBLK];
__device__ unsigned int g_count;   // zero-init at load; reset by last block each run

// One warp per row; lane owns 16 float4 slots, processed as two batches of 8
// with an explicit register prefetch batch. __launch_bounds__(256,4) grants a
// 64-reg budget so ptxas can actually keep 8 LDG.128 in flight per warp
// (at regs=32 it silently re-serialized them — R5 post-mortem).
__global__ __launch_bounds__(NTHR, 4) void fused_loss_kernel(
    const float* __restrict__ x,
    const int* __restrict__ pol,      // int32 (JAX x64-disabled downcasts int64)
    const float* __restrict__ s,
    float* __restrict__ out)
{
    const float4* __restrict__ x4 = (const float4*)x;
    const float4* __restrict__ s4 = (const float4*)s;
    const int tid  = threadIdx.x;
    const int wid  = tid >> 5;
    const int lane = tid & 31;

    const int row = blockIdx.x * WARPS_PER_BLK + wid;   // < 16384 always

    int p = __ldg(&pol[row]);
    p = min(max(p, 0), 2);                              // keep gather in-bounds

    const float4* __restrict__ xr = x4 + row * D4;
    const float4* __restrict__ sr = s4 + p * D4;

    float a0 = 0.f, a1 = 0.f, a2 = 0.f, a3 = 0.f;

#pragma unroll
    for (int half = 0; half < 2; half++) {
        const int base = half * 256 + lane;
        float4 xv[8];
#pragma unroll
        for (int k = 0; k < 8; k++)                     // 8 independent DRAM loads
            xv[k] = xr[base + 32 * k];
#pragma unroll
        for (int k = 0; k < 8; k++) {
            float4 sv = __ldg(&sr[base + 32 * k]);      // L1-hot 24KB table
            float d0 = xv[k].x - sv.x;
            float d1 = xv[k].y - sv.y;
            float d2 = xv[k].z - sv.z;
            float d3 = xv[k].w - sv.w;
            a0 += d0 * d0;  a1 += d1 * d1;
            a2 += d2 * d2;  a3 += d3 * d3;
        }
    }
    float acc = (a0 + a1) + (a2 + a3);

    // warp reduce
#pragma unroll
    for (int off = 16; off > 0; off >>= 1)
        acc += __shfl_down_sync(0xFFFFFFFFu, acc, off);

    __shared__ float wsum[WARPS_PER_BLK];
    if (lane == 0) wsum[wid] = acc;
    __syncthreads();

    __shared__ unsigned int s_islast;
    if (tid == 0) {
        float bsum = 0.f;
#pragma unroll
        for (int w = 0; w < WARPS_PER_BLK; w++) bsum += wsum[w];
        g_partials[blockIdx.x] = bsum;
        __threadfence();
        unsigned int prev = atomicAdd(&g_count, 1u);
        s_islast = (prev == NBLK - 1) ? 1u : 0u;
    }
    __syncthreads();
    if (!s_islast) return;

    // ---- last block: fold partials + cos^2 terms ----
    float racc = 0.0f;
    for (int j = tid; j < NBLK; j += NTHR) racc += g_partials[j];

    // cos_(a,b) = dot(a,b) / sqrt(||a||^2) * sqrt(||b||^2) (reference precedence)
    // => cos_^2 = dot^2 * ||b||^2 / ||a||^2
    float n0 = 0.f, n1 = 0.f, n2 = 0.f, d01 = 0.f, d02 = 0.f, d12 = 0.f;
    for (int j = tid; j < D_DIM; j += NTHR) {
        float a = s[j];
        float b = s[D_DIM + j];
        float c = s[2 * D_DIM + j];
        n0  += a * a;  n1  += b * b;  n2  += c * c;
        d01 += a * b;  d02 += a * c;  d12 += b * c;
    }

    __shared__ float rm[7][NTHR];
    rm[0][tid] = racc;
    rm[1][tid] = n0;  rm[2][tid] = n1;  rm[3][tid] = n2;
    rm[4][tid] = d01; rm[5][tid] = d02; rm[6][tid] = d12;
    __syncthreads();
#pragma unroll
    for (int st = NTHR / 2; st > 0; st >>= 1) {
        if (tid < st) {
#pragma unroll
            for (int k = 0; k < 7; k++) rm[k][tid] += rm[k][tid + st];
        }
        __syncthreads();
    }

    if (tid == 0) {
        float L   = rm[0][0];
        float N0  = rm[1][0], N1 = rm[2][0], N2 = rm[3][0];
        float D01 = rm[4][0], D02 = rm[5][0], D12 = rm[6][0];
        float c01 = D01 * D01 * (N1 / N0);
        float c02 = D02 * D02 * (N2 / N0);
        float c12 = D12 * D12 * (N2 / N1);
        out[0] = L + c01 + c02 + c12;
        g_count = 0;                 // reset for next graph replay
    }
}

extern "C" void kernel_launch(void* const* d_in, const int* in_sizes, int n_in,
                              void* d_out, int out_size)
{
    const float* x   = (const float*)d_in[0];   // inputs [16384, 2048] f32
    const int*   pol = (const int*)d_in[1];     // polarity [16384] int32
    const float* s   = (const float*)d_in[2];   // standar_score [3, 2048] f32
    float* out = (float*)d_out;

    fused_loss_kernel<<<NBLK, NTHR>>>(x, pol, s, out);
}

// round 7
// speedup vs baseline: 1.0124x; 1.0124x over previous
#include <cuda_runtime.h>

// Problem shape (fixed by the dataset)
#define B_ROWS   16384
#define D_DIM    2048
#define D4       (D_DIM / 4)          // 512 float4 per row
#define NBLK     2048
#define NTHR     256                   // 8 warps/block, 1 warp per row
#define WARPS_PER_BLK (NTHR / 32)
#define S_TOT4   (3 * D4)              // 1536 float4 = 24KB of standar_score

__device__ float g_partials[NBLK];
__device__ unsigned int g_count;   // zero-init at load; reset by last block each run

__device__ __forceinline__ float4 ldcs4(const float4* p) {
    return __ldcs(p);                  // evict-first: x is single-use stream
}

// One warp per row. standar_score staged in SMEM -> the per-element gather
// uses the smem crossbar (LDS.128) instead of L1tex, halving L1tex wavefront
// traffic (R6 post-mortem: L1tex replay serialization, not MLP, caps BW).
__global__ __launch_bounds__(NTHR, 4) void fused_loss_kernel(
    const float* __restrict__ x,
    const int* __restrict__ pol,      // int32 (JAX x64-disabled downcasts int64)
    const float* __restrict__ s,
    float* __restrict__ out)
{
    __shared__ float4 s_sm[S_TOT4];   // 24KB staged score table

    const float4* __restrict__ x4 = (const float4*)x;
    const float4* __restrict__ s4 = (const float4*)s;
    const int tid  = threadIdx.x;
    const int wid  = tid >> 5;
    const int lane = tid & 31;

    // cooperative stage: 1536 float4 / 256 threads = 6 each (L2-hot source)
#pragma unroll
    for (int j = 0; j < S_TOT4 / NTHR; j++)
        s_sm[tid + j * NTHR] = __ldg(&s4[tid + j * NTHR]);

    const int row = blockIdx.x * WARPS_PER_BLK + wid;   // < 16384 always
    int p = __ldg(&pol[row]);
    p = min(max(p, 0), 2);                              // keep gather in-bounds

    const float4* __restrict__ xr = x4 + row * D4;
    const float4* sp = s_sm + p * D4;

    __syncthreads();                                    // table ready

    float a0 = 0.f, a1 = 0.f, a2 = 0.f, a3 = 0.f;

#pragma unroll
    for (int half = 0; half < 2; half++) {
        const int base = half * 256 + lane;
        float4 xv[8];
#pragma unroll
        for (int k = 0; k < 8; k++)                     // 8 independent DRAM loads
            xv[k] = ldcs4(&xr[base + 32 * k]);
#pragma unroll
        for (int k = 0; k < 8; k++) {
            float4 sv = sp[base + 32 * k];              // LDS.128, conflict-free
            float d0 = xv[k].x - sv.x;
            float d1 = xv[k].y - sv.y;
            float d2 = xv[k].z - sv.z;
            float d3 = xv[k].w - sv.w;
            a0 += d0 * d0;  a1 += d1 * d1;
            a2 += d2 * d2;  a3 += d3 * d3;
        }
    }
    float acc = (a0 + a1) + (a2 + a3);

    // warp reduce
#pragma unroll
    for (int off = 16; off > 0; off >>= 1)
        acc += __shfl_down_sync(0xFFFFFFFFu, acc, off);

    __shared__ float wsum[WARPS_PER_BLK];
    if (lane == 0) wsum[wid] = acc;
    __syncthreads();

    __shared__ unsigned int s_islast;
    if (tid == 0) {
        float bsum = 0.f;
#pragma unroll
        for (int w = 0; w < WARPS_PER_BLK; w++) bsum += wsum[w];
        g_partials[blockIdx.x] = bsum;
        __threadfence();
        unsigned int prev = atomicAdd(&g_count, 1u);
        s_islast = (prev == NBLK - 1) ? 1u : 0u;
    }
    __syncthreads();
    if (!s_islast) return;

    // ---- last block: fold partials + cos^2 terms ----
    float racc = 0.0f;
    for (int j = tid; j < NBLK; j += NTHR) racc += g_partials[j];

    // cos_(a,b) = dot(a,b) / sqrt(||a||^2) * sqrt(||b||^2) (reference precedence)
    // => cos_^2 = dot^2 * ||b||^2 / ||a||^2
    float n0 = 0.f, n1 = 0.f, n2 = 0.f, d01 = 0.f, d02 = 0.f, d12 = 0.f;
    for (int j = tid; j < D_DIM; j += NTHR) {
        float a = s[j];
        float b = s[D_DIM + j];
        float c = s[2 * D_DIM + j];
        n0  += a * a;  n1  += b * b;  n2  += c * c;
        d01 += a * b;  d02 += a * c;  d12 += b * c;
    }

    __shared__ float rm[7][NTHR];
    rm[0][tid] = racc;
    rm[1][tid] = n0;  rm[2][tid] = n1;  rm[3][tid] = n2;
    rm[4][tid] = d01; rm[5][tid] = d02; rm[6][tid] = d12;
    __syncthreads();
#pragma unroll
    for (int st = NTHR / 2; st > 0; st >>= 1) {
        if (tid < st) {
#pragma unroll
            for (int k = 0; k < 7; k++) rm[k][tid] += rm[k][tid + st];
        }
        __syncthreads();
    }

    if (tid == 0) {
        float L   = rm[0][0];
        float N0  = rm[1][0], N1 = rm[2][0], N2 = rm[3][0];
        float D01 = rm[4][0], D02 = rm[5][0], D12 = rm[6][0];
        float c01 = D01 * D01 * (N1 / N0);
        float c02 = D02 * D02 * (N2 / N0);
        float c12 = D12 * D12 * (N2 / N1);
        out[0] = L + c01 + c02 + c12;
        g_count = 0;                 // reset for next graph replay
    }
}

extern "C" void kernel_launch(void* const* d_in, const int* in_sizes, int n_in,
                              void* d_out, int out_size)
{
    const float* x   = (const float*)d_in[0];   // inputs [16384, 2048] f32
    const int*   pol = (const int*)d_in[1];     // polarity [16384] int32
    const float* s   = (const float*)d_in[2];   // standar_score [3, 2048] f32
    float* out = (float*)d_out;

    fused_loss_kernel<<<NBLK, NTHR>>>(x, pol, s, out);
}